// round 1
// baseline (speedup 1.0000x reference)
#include <cuda_runtime.h>

// Problem constants
#define BB   2
#define SS   2048
#define DD   1024
#define HH   16
#define DKV  64           // DK == DV == 64
#define BH   (BB*HH)      // 32

static const size_t OUT_OFF = (size_t)BB * SS * DD;   // 4,194,304 floats (out), then attention

// Scratch: [B,H,S,64] projections + [B,S,H*64] attention output
__device__ float g_q[BH * SS * DKV];
__device__ float g_k[BH * SS * DKV];
__device__ float g_v[BH * SS * DKV];
__device__ float g_ao[(size_t)BB * SS * HH * DKV];

// ---------------------------------------------------------------------------
// Generic 64x64-tile fp32 GEMM with bias: C = A[M,K] @ W[K,N] + bias
// 256 threads, 4x4 micro-tile per thread, BK=16.
// asel: 0 -> use A param, 1 -> read from g_ao
// mode: 0 -> plain row-major C[m*N+n]
//       1/2/3 -> scatter to g_q/g_k/g_v as [B,H,S,64] (m=b*S+s, n=h*64+d)
// M=4096, N=1024, K=1024 for all uses of this kernel.
// ---------------------------------------------------------------------------
__global__ __launch_bounds__(256) void gemm_proj_kernel(
    const float* __restrict__ A, const float* __restrict__ W,
    const float* __restrict__ bias, float* __restrict__ Cplain,
    int mode, int asel)
{
    const int M = BB * SS, N = HH * DKV, K = DD;
    (void)M;
    __shared__ float As[16][68];   // k-major, padded (16B-aligned rows)
    __shared__ float Ws[16][64];   // k-major

    const float* __restrict__ Ap = asel ? g_ao : A;

    int row0 = blockIdx.y << 6;
    int col0 = blockIdx.x << 6;
    int t  = threadIdx.x;
    int tx = t & 15, ty = t >> 4;
    int ar = t >> 2, ac = (t & 3) << 2;     // A tile load: row 0..63, col group
    int wr = t >> 4, wc = (t & 15) << 2;    // W tile load: row 0..15, col group

    float acc[4][4] = {};

    for (int k0 = 0; k0 < K; k0 += 16) {
        float4 av = *(const float4*)(Ap + (size_t)(row0 + ar) * K + k0 + ac);
        As[ac + 0][ar] = av.x;
        As[ac + 1][ar] = av.y;
        As[ac + 2][ar] = av.z;
        As[ac + 3][ar] = av.w;
        *(float4*)&Ws[wr][wc] =
            *(const float4*)(W + (size_t)(k0 + wr) * N + col0 + wc);
        __syncthreads();

        #pragma unroll
        for (int kk = 0; kk < 16; kk++) {
            float4 a4 = *(const float4*)&As[kk][ty << 2];
            float4 b4 = *(const float4*)&Ws[kk][tx << 2];
            float a[4] = {a4.x, a4.y, a4.z, a4.w};
            float b[4] = {b4.x, b4.y, b4.z, b4.w};
            #pragma unroll
            for (int i = 0; i < 4; i++)
                #pragma unroll
                for (int j = 0; j < 4; j++)
                    acc[i][j] += a[i] * b[j];
        }
        __syncthreads();
    }

    #pragma unroll
    for (int i = 0; i < 4; i++) {
        int m = row0 + (ty << 2) + i;
        #pragma unroll
        for (int j = 0; j < 4; j++) {
            int n = col0 + (tx << 2) + j;
            float v = acc[i][j] + bias[n];
            if (mode == 0) {
                Cplain[(size_t)m * N + n] = v;
            } else {
                int b = m >> 11, s = m & (SS - 1);
                int h = n >> 6,  d = n & 63;
                float* dst = (mode == 1) ? g_q : (mode == 2) ? g_k : g_v;
                dst[(((size_t)(b * HH + h) * SS + s) << 6) + d] = v;
            }
        }
    }
}

// ---------------------------------------------------------------------------
// Scores: energy[bh][i][j] = dot(Q[bh][i], K[bh][j]) / 8, masked -> attn slice
// grid (S/64 j-tiles, S/64 i-tiles, BH), 256 threads, 4x4 micro-tile, K=64 full
// ---------------------------------------------------------------------------
__global__ __launch_bounds__(256) void score_kernel(
    const int* __restrict__ mask, float* __restrict__ attn)
{
    __shared__ float Qs[64][68];   // k-major: Qs[k][i]
    __shared__ float Ks[64][68];   // k-major: Ks[k][j]

    int bh = blockIdx.z;
    int b  = bh >> 4;
    int i0 = blockIdx.y << 6;
    int j0 = blockIdx.x << 6;
    const float* Qg = g_q + ((size_t)bh * SS << 6);
    const float* Kg = g_k + ((size_t)bh * SS << 6);

    int t = threadIdx.x;
    // load 64x64 tiles, transposing into k-major smem
    #pragma unroll
    for (int it = 0; it < 4; it++) {
        int f   = (it << 8) + t;     // float4 id 0..1023
        int row = f >> 4;            // 0..63
        int kc  = (f & 15) << 2;     // k column base
        float4 q4 = *(const float4*)(Qg + ((size_t)(i0 + row) << 6) + kc);
        Qs[kc + 0][row] = q4.x; Qs[kc + 1][row] = q4.y;
        Qs[kc + 2][row] = q4.z; Qs[kc + 3][row] = q4.w;
        float4 k4 = *(const float4*)(Kg + ((size_t)(j0 + row) << 6) + kc);
        Ks[kc + 0][row] = k4.x; Ks[kc + 1][row] = k4.y;
        Ks[kc + 2][row] = k4.z; Ks[kc + 3][row] = k4.w;
    }
    __syncthreads();

    int tx = t & 15, ty = t >> 4;
    float acc[4][4] = {};
    #pragma unroll 8
    for (int kk = 0; kk < 64; kk++) {
        float4 a4 = *(const float4*)&Qs[kk][ty << 2];
        float4 b4 = *(const float4*)&Ks[kk][tx << 2];
        float a[4] = {a4.x, a4.y, a4.z, a4.w};
        float b[4] = {b4.x, b4.y, b4.z, b4.w};
        #pragma unroll
        for (int i = 0; i < 4; i++)
            #pragma unroll
            for (int j = 0; j < 4; j++)
                acc[i][j] += a[i] * b[j];
    }

    const float inv_temp = 0.125f;   // 1/sqrt(64)
    #pragma unroll
    for (int i = 0; i < 4; i++) {
        int ii = i0 + (ty << 2) + i;
        #pragma unroll
        for (int j = 0; j < 4; j++) {
            int jj = j0 + (tx << 2) + j;
            float e = acc[i][j] * inv_temp;
            if (mask[((size_t)b * SS + ii) * SS + jj] == 0) e = -10000.0f;
            attn[((size_t)bh * SS + ii) * SS + jj] = e;
        }
    }
}

// ---------------------------------------------------------------------------
// In-place row softmax over the attention slice. One block per row (2048 f32).
// ---------------------------------------------------------------------------
__global__ __launch_bounds__(256) void softmax_kernel(float* __restrict__ attn)
{
    float* p = attn + (size_t)blockIdx.x * SS;
    int t = threadIdx.x;
    float4 a = ((const float4*)p)[t];
    float4 c = ((const float4*)p)[t + 256];

    float m = fmaxf(fmaxf(fmaxf(a.x, a.y), fmaxf(a.z, a.w)),
                    fmaxf(fmaxf(c.x, c.y), fmaxf(c.z, c.w)));
    #pragma unroll
    for (int o = 16; o; o >>= 1) m = fmaxf(m, __shfl_xor_sync(~0u, m, o));

    __shared__ float redm[8], reds[8];
    int w = t >> 5, l = t & 31;
    if (l == 0) redm[w] = m;
    __syncthreads();
    m = redm[0];
    #pragma unroll
    for (int i = 1; i < 8; i++) m = fmaxf(m, redm[i]);

    a.x = __expf(a.x - m); a.y = __expf(a.y - m);
    a.z = __expf(a.z - m); a.w = __expf(a.w - m);
    c.x = __expf(c.x - m); c.y = __expf(c.y - m);
    c.z = __expf(c.z - m); c.w = __expf(c.w - m);

    float s = (a.x + a.y) + (a.z + a.w) + (c.x + c.y) + (c.z + c.w);
    #pragma unroll
    for (int o = 16; o; o >>= 1) s += __shfl_xor_sync(~0u, s, o);
    if (l == 0) reds[w] = s;
    __syncthreads();
    s = reds[0];
    #pragma unroll
    for (int i = 1; i < 8; i++) s += reds[i];

    float inv = 1.0f / s;
    a.x *= inv; a.y *= inv; a.z *= inv; a.w *= inv;
    c.x *= inv; c.y *= inv; c.z *= inv; c.w *= inv;
    ((float4*)p)[t]       = a;
    ((float4*)p)[t + 256] = c;
}

// ---------------------------------------------------------------------------
// AV: per (b,h): g_ao[b,s,h*64+d] = attn[bh] @ V[bh],  [S,S]@[S,64]
// grid (S/64 row-tiles, BH), 256 threads, 4x4 micro-tile, BK=16
// ---------------------------------------------------------------------------
__global__ __launch_bounds__(256) void gemm_av_kernel(const float* __restrict__ attn)
{
    __shared__ float As[16][68];   // k-major: As[k][i]
    __shared__ float Ws[16][64];   // k-major: V rows

    int bh = blockIdx.y;
    int b  = bh >> 4, h = bh & 15;
    int row0 = blockIdx.x << 6;
    const float* A = attn + (size_t)bh * SS * SS;
    const float* V = g_v + ((size_t)bh * SS << 6);

    int t  = threadIdx.x;
    int tx = t & 15, ty = t >> 4;
    int ar = t >> 2, ac = (t & 3) << 2;
    int wr = t >> 4, wc = (t & 15) << 2;

    float acc[4][4] = {};
    for (int k0 = 0; k0 < SS; k0 += 16) {
        float4 av = *(const float4*)(A + (size_t)(row0 + ar) * SS + k0 + ac);
        As[ac + 0][ar] = av.x;
        As[ac + 1][ar] = av.y;
        As[ac + 2][ar] = av.z;
        As[ac + 3][ar] = av.w;
        *(float4*)&Ws[wr][wc] =
            *(const float4*)(V + ((size_t)(k0 + wr) << 6) + wc);
        __syncthreads();

        #pragma unroll
        for (int kk = 0; kk < 16; kk++) {
            float4 a4 = *(const float4*)&As[kk][ty << 2];
            float4 b4 = *(const float4*)&Ws[kk][tx << 2];
            float a[4] = {a4.x, a4.y, a4.z, a4.w};
            float bv[4] = {b4.x, b4.y, b4.z, b4.w};
            #pragma unroll
            for (int i = 0; i < 4; i++)
                #pragma unroll
                for (int j = 0; j < 4; j++)
                    acc[i][j] += a[i] * bv[j];
        }
        __syncthreads();
    }

    #pragma unroll
    for (int i = 0; i < 4; i++) {
        int s = row0 + (ty << 2) + i;
        #pragma unroll
        for (int j = 0; j < 4; j++) {
            int d = (tx << 2) + j;
            g_ao[(((size_t)(b * SS + s)) << 10) + (h << 6) + d] = acc[i][j];
        }
    }
}

// ---------------------------------------------------------------------------
extern "C" void kernel_launch(void* const* d_in, const int* in_sizes, int n_in,
                              void* d_out, int out_size)
{
    const float* query = (const float*)d_in[0];
    const float* key   = (const float*)d_in[1];
    const float* value = (const float*)d_in[2];
    const int*   mask  = (const int*)  d_in[3];
    const float* Wq = (const float*)d_in[4];
    const float* bq = (const float*)d_in[5];
    const float* Wk = (const float*)d_in[6];
    const float* bk = (const float*)d_in[7];
    const float* Wv = (const float*)d_in[8];
    const float* bv = (const float*)d_in[9];
    const float* Wo = (const float*)d_in[10];
    const float* bo = (const float*)d_in[11];

    float* out  = (float*)d_out;
    float* attn = out + OUT_OFF;

    dim3 gProj(HH * DKV / 64, BB * SS / 64);   // (16, 64)
    gemm_proj_kernel<<<gProj, 256>>>(query, Wq, bq, nullptr, 1, 0);
    gemm_proj_kernel<<<gProj, 256>>>(key,   Wk, bk, nullptr, 2, 0);
    gemm_proj_kernel<<<gProj, 256>>>(value, Wv, bv, nullptr, 3, 0);

    dim3 gScore(SS / 64, SS / 64, BH);          // (32, 32, 32)
    score_kernel<<<gScore, 256>>>(mask, attn);

    softmax_kernel<<<BH * SS, 256>>>(attn);     // 65536 rows

    dim3 gAV(SS / 64, BH);                      // (32, 32)
    gemm_av_kernel<<<gAV, 256>>>(attn);

    gemm_proj_kernel<<<gProj, 256>>>(nullptr, Wo, bo, out, 0, 1);
}

// round 2
// speedup vs baseline: 1.9516x; 1.9516x over previous
#include <cuda_runtime.h>
#include <cstdint>

#define BB   2
#define SS   2048
#define DD   1024
#define HH   16
#define DKV  64
#define BH   (BB*HH)

static const size_t OUT_OFF = (size_t)BB * SS * DD;   // out floats, then attention

// Scratch
__device__ float g_q [(size_t)BH * SS * DKV];          // [bh][s][64]
__device__ float g_k [(size_t)BH * SS * DKV];          // [bh][s][64]
__device__ float g_vT[(size_t)BH * DKV * SS];          // [bh][d][s]  (transposed!)
__device__ float g_ao[(size_t)BB * SS * HH * DKV];     // [b][s][h*64+d]

// ---------------------------------------------------------------------------
__device__ __forceinline__ uint32_t f2tf32(float x) {
    uint32_t u;
    asm("cvt.rna.tf32.f32 %0, %1;" : "=r"(u) : "f"(x));
    return u;
}

__device__ __forceinline__ void mma8(float c[4], const uint32_t a[4], const uint32_t b[2]) {
    asm volatile(
        "mma.sync.aligned.m16n8k8.row.col.f32.tf32.tf32.f32 "
        "{%0,%1,%2,%3}, {%4,%5,%6,%7}, {%8,%9}, {%0,%1,%2,%3};\n"
        : "+f"(c[0]), "+f"(c[1]), "+f"(c[2]), "+f"(c[3])
        : "r"(a[0]), "r"(a[1]), "r"(a[2]), "r"(a[3]), "r"(b[0]), "r"(b[1]));
}

// Compute one BK=32 slab. As: [128][LDA] row-major (m,k). acc: warp tile 32x32.
// B stored [n][LDB] (k fastest within an n row).
template<int LDA, int LDB>
__device__ __forceinline__ void compute_Bnk(
    const float* __restrict__ As, const float* __restrict__ Bs,
    float acc[2][4][4], int wm, int wn, int g, int t)
{
    #pragma unroll
    for (int kk = 0; kk < 4; kk++) {
        int k0 = kk * 8;
        uint32_t a[2][4];
        #pragma unroll
        for (int mf = 0; mf < 2; mf++) {
            const float* p = As + (wm * 32 + mf * 16 + g) * LDA + k0 + t;
            a[mf][0] = __float_as_uint(p[0]);
            a[mf][1] = __float_as_uint(p[8 * LDA]);
            a[mf][2] = __float_as_uint(p[4]);
            a[mf][3] = __float_as_uint(p[8 * LDA + 4]);
        }
        uint32_t bb[4][2];
        #pragma unroll
        for (int nf = 0; nf < 4; nf++) {
            const float* p = Bs + (wn * 32 + nf * 8 + g) * LDB + k0 + t;
            bb[nf][0] = __float_as_uint(p[0]);
            bb[nf][1] = __float_as_uint(p[4]);
        }
        #pragma unroll
        for (int mf = 0; mf < 2; mf++)
            #pragma unroll
            for (int nf = 0; nf < 4; nf++)
                mma8(acc[mf][nf], a[mf], bb[nf]);
    }
}

// B stored [k][LDB] (n fastest within a k row).
template<int LDA, int LDB>
__device__ __forceinline__ void compute_Bkn(
    const float* __restrict__ As, const float* __restrict__ Bs,
    float acc[2][4][4], int wm, int wn, int g, int t)
{
    #pragma unroll
    for (int kk = 0; kk < 4; kk++) {
        int k0 = kk * 8;
        uint32_t a[2][4];
        #pragma unroll
        for (int mf = 0; mf < 2; mf++) {
            const float* p = As + (wm * 32 + mf * 16 + g) * LDA + k0 + t;
            a[mf][0] = __float_as_uint(p[0]);
            a[mf][1] = __float_as_uint(p[8 * LDA]);
            a[mf][2] = __float_as_uint(p[4]);
            a[mf][3] = __float_as_uint(p[8 * LDA + 4]);
        }
        uint32_t bb[4][2];
        #pragma unroll
        for (int nf = 0; nf < 4; nf++) {
            int n = wn * 32 + nf * 8 + g;
            bb[nf][0] = __float_as_uint(Bs[(k0 + t) * LDB + n]);
            bb[nf][1] = __float_as_uint(Bs[(k0 + t + 4) * LDB + n]);
        }
        #pragma unroll
        for (int mf = 0; mf < 2; mf++)
            #pragma unroll
            for (int nf = 0; nf < 4; nf++)
                mma8(acc[mf][nf], a[mf], bb[nf]);
    }
}

// ---------------------------------------------------------------------------
// Projection GEMM: C[4096,1024] = A @ W + bias. Tile 128x64, BK=32.
// mode 0: plain C. mode 1/2: scatter to g_q/g_k [bh][s][64]. mode 3: g_vT [bh][d][s].
// asel 1: A = g_ao.
// ---------------------------------------------------------------------------
__global__ __launch_bounds__(256) void gemm_proj(
    const float* __restrict__ A, const float* __restrict__ W,
    const float* __restrict__ bias, float* __restrict__ Cplain,
    int mode, int asel)
{
    const int K = DD, N = DD;
    __shared__ __align__(16) float As[128 * 36];
    __shared__ __align__(16) float Ws[32 * 72];

    const float* __restrict__ Ap = asel ? g_ao : A;
    int row0 = blockIdx.y * 128, col0 = blockIdx.x * 64;
    int tid = threadIdx.x, lane = tid & 31, wid = tid >> 5;
    int wm = wid & 3, wn = wid >> 2, g = lane >> 2, t = lane & 3;

    float acc[2][4][4] = {};

    for (int k0 = 0; k0 < K; k0 += 32) {
        #pragma unroll
        for (int i = 0; i < 4; i++) {
            int f = tid + i * 256;
            int r = f >> 3, c = (f & 7) * 4;
            float4 v = *(const float4*)(Ap + (size_t)(row0 + r) * K + k0 + c);
            float4 w;
            w.x = __uint_as_float(f2tf32(v.x));
            w.y = __uint_as_float(f2tf32(v.y));
            w.z = __uint_as_float(f2tf32(v.z));
            w.w = __uint_as_float(f2tf32(v.w));
            *(float4*)(As + r * 36 + c) = w;
        }
        #pragma unroll
        for (int i = 0; i < 2; i++) {
            int f = tid + i * 256;
            int r = f >> 4, c = (f & 15) * 4;
            float4 v = *(const float4*)(W + (size_t)(k0 + r) * N + col0 + c);
            float4 w;
            w.x = __uint_as_float(f2tf32(v.x));
            w.y = __uint_as_float(f2tf32(v.y));
            w.z = __uint_as_float(f2tf32(v.z));
            w.w = __uint_as_float(f2tf32(v.w));
            *(float4*)(Ws + r * 72 + c) = w;
        }
        __syncthreads();
        compute_Bkn<36, 72>(As, Ws, acc, wm, wn, g, t);
        __syncthreads();
    }

    #pragma unroll
    for (int mf = 0; mf < 2; mf++) {
        #pragma unroll
        for (int nf = 0; nf < 4; nf++) {
            int n = col0 + wn * 32 + nf * 8 + 2 * t;
            float b0 = bias[n], b1 = bias[n + 1];
            #pragma unroll
            for (int h = 0; h < 2; h++) {
                int m = row0 + wm * 32 + mf * 16 + g + h * 8;
                float v0 = acc[mf][nf][h * 2 + 0] + b0;
                float v1 = acc[mf][nf][h * 2 + 1] + b1;
                if (mode == 0) {
                    float2* p = (float2*)(Cplain + (size_t)m * N + n);
                    *p = make_float2(v0, v1);
                } else {
                    int b = m >> 11, s = m & (SS - 1);
                    int hh = n >> 6, d = n & 63;
                    if (mode != 3) {
                        float* dst = (mode == 1) ? g_q : g_k;
                        float2* p = (float2*)(dst + ((((size_t)(b * HH + hh)) * SS + s) << 6) + d);
                        *p = make_float2(v0, v1);
                    } else {
                        float* dst = g_vT + ((size_t)(b * HH + hh) * DKV + d) * SS + s;
                        dst[0] = v0;
                        dst[SS] = v1;
                    }
                }
            }
        }
    }
}

// ---------------------------------------------------------------------------
// Scores: energy = Q @ K^T / 8, masked -> attn. Tile 128(i) x 64(j), K=64.
// ---------------------------------------------------------------------------
__global__ __launch_bounds__(256) void score_kernel(
    const int* __restrict__ mask, float* __restrict__ attn)
{
    __shared__ __align__(16) float Qs[128 * 36];
    __shared__ __align__(16) float Ks[64 * 36];

    int bh = blockIdx.z, b = bh >> 4;
    int i0 = blockIdx.y * 128, j0 = blockIdx.x * 64;
    const float* Qg = g_q + ((size_t)bh * SS) * 64;
    const float* Kg = g_k + ((size_t)bh * SS) * 64;

    int tid = threadIdx.x, lane = tid & 31, wid = tid >> 5;
    int wm = wid & 3, wn = wid >> 2, g = lane >> 2, t = lane & 3;

    float acc[2][4][4] = {};

    for (int k0 = 0; k0 < 64; k0 += 32) {
        #pragma unroll
        for (int i = 0; i < 4; i++) {
            int f = tid + i * 256;
            int r = f >> 3, c = (f & 7) * 4;
            float4 v = *(const float4*)(Qg + (size_t)(i0 + r) * 64 + k0 + c);
            float4 w;
            w.x = __uint_as_float(f2tf32(v.x));
            w.y = __uint_as_float(f2tf32(v.y));
            w.z = __uint_as_float(f2tf32(v.z));
            w.w = __uint_as_float(f2tf32(v.w));
            *(float4*)(Qs + r * 36 + c) = w;
        }
        #pragma unroll
        for (int i = 0; i < 2; i++) {
            int f = tid + i * 256;
            int r = f >> 3, c = (f & 7) * 4;
            float4 v = *(const float4*)(Kg + (size_t)(j0 + r) * 64 + k0 + c);
            float4 w;
            w.x = __uint_as_float(f2tf32(v.x));
            w.y = __uint_as_float(f2tf32(v.y));
            w.z = __uint_as_float(f2tf32(v.z));
            w.w = __uint_as_float(f2tf32(v.w));
            *(float4*)(Ks + r * 36 + c) = w;
        }
        __syncthreads();
        compute_Bnk<36, 36>(Qs, Ks, acc, wm, wn, g, t);
        __syncthreads();
    }

    const float inv_temp = 0.125f;
    #pragma unroll
    for (int mf = 0; mf < 2; mf++) {
        #pragma unroll
        for (int nf = 0; nf < 4; nf++) {
            int jj = j0 + wn * 32 + nf * 8 + 2 * t;
            #pragma unroll
            for (int h = 0; h < 2; h++) {
                int ii = i0 + wm * 32 + mf * 16 + g + h * 8;
                float e0 = acc[mf][nf][h * 2 + 0] * inv_temp;
                float e1 = acc[mf][nf][h * 2 + 1] * inv_temp;
                int2 mm = *(const int2*)(mask + ((size_t)b * SS + ii) * SS + jj);
                if (mm.x == 0) e0 = -10000.0f;
                if (mm.y == 0) e1 = -10000.0f;
                *(float2*)(attn + ((size_t)bh * SS + ii) * SS + jj) = make_float2(e0, e1);
            }
        }
    }
}

// ---------------------------------------------------------------------------
// In-place row softmax over the attention slice. One block per row (2048 f32).
// ---------------------------------------------------------------------------
__global__ __launch_bounds__(256) void softmax_kernel(float* __restrict__ attn)
{
    float* p = attn + (size_t)blockIdx.x * SS;
    int t = threadIdx.x;
    float4 a = ((const float4*)p)[t];
    float4 c = ((const float4*)p)[t + 256];

    float m = fmaxf(fmaxf(fmaxf(a.x, a.y), fmaxf(a.z, a.w)),
                    fmaxf(fmaxf(c.x, c.y), fmaxf(c.z, c.w)));
    #pragma unroll
    for (int o = 16; o; o >>= 1) m = fmaxf(m, __shfl_xor_sync(~0u, m, o));

    __shared__ float redm[8], reds[8];
    int w = t >> 5, l = t & 31;
    if (l == 0) redm[w] = m;
    __syncthreads();
    m = redm[0];
    #pragma unroll
    for (int i = 1; i < 8; i++) m = fmaxf(m, redm[i]);

    a.x = __expf(a.x - m); a.y = __expf(a.y - m);
    a.z = __expf(a.z - m); a.w = __expf(a.w - m);
    c.x = __expf(c.x - m); c.y = __expf(c.y - m);
    c.z = __expf(c.z - m); c.w = __expf(c.w - m);

    float s = (a.x + a.y) + (a.z + a.w) + (c.x + c.y) + (c.z + c.w);
    #pragma unroll
    for (int o = 16; o; o >>= 1) s += __shfl_xor_sync(~0u, s, o);
    if (l == 0) reds[w] = s;
    __syncthreads();
    s = reds[0];
    #pragma unroll
    for (int i = 1; i < 8; i++) s += reds[i];

    float inv = 1.0f / s;
    a.x *= inv; a.y *= inv; a.z *= inv; a.w *= inv;
    c.x *= inv; c.y *= inv; c.z *= inv; c.w *= inv;
    ((float4*)p)[t]       = a;
    ((float4*)p)[t + 256] = c;
}

// ---------------------------------------------------------------------------
// AV: g_ao[b,s,h*64+d] = attn[bh] @ V[bh].  M=2048, K=2048, N=64. Tile 128x64.
// ---------------------------------------------------------------------------
__global__ __launch_bounds__(256) void gemm_av(const float* __restrict__ attn)
{
    __shared__ __align__(16) float As[128 * 36];
    __shared__ __align__(16) float Vs[64 * 36];

    int bh = blockIdx.y, b = bh >> 4, hh = bh & 15;
    int row0 = blockIdx.x * 128;
    const float* Ag = attn + (size_t)bh * SS * SS;
    const float* Vg = g_vT + (size_t)bh * DKV * SS;

    int tid = threadIdx.x, lane = tid & 31, wid = tid >> 5;
    int wm = wid & 3, wn = wid >> 2, g = lane >> 2, t = lane & 3;

    float acc[2][4][4] = {};

    for (int k0 = 0; k0 < SS; k0 += 32) {
        #pragma unroll
        for (int i = 0; i < 4; i++) {
            int f = tid + i * 256;
            int r = f >> 3, c = (f & 7) * 4;
            float4 v = *(const float4*)(Ag + (size_t)(row0 + r) * SS + k0 + c);
            float4 w;
            w.x = __uint_as_float(f2tf32(v.x));
            w.y = __uint_as_float(f2tf32(v.y));
            w.z = __uint_as_float(f2tf32(v.z));
            w.w = __uint_as_float(f2tf32(v.w));
            *(float4*)(As + r * 36 + c) = w;
        }
        #pragma unroll
        for (int i = 0; i < 2; i++) {
            int f = tid + i * 256;
            int r = f >> 3, c = (f & 7) * 4;
            float4 v = *(const float4*)(Vg + (size_t)r * SS + k0 + c);
            float4 w;
            w.x = __uint_as_float(f2tf32(v.x));
            w.y = __uint_as_float(f2tf32(v.y));
            w.z = __uint_as_float(f2tf32(v.z));
            w.w = __uint_as_float(f2tf32(v.w));
            *(float4*)(Vs + r * 36 + c) = w;
        }
        __syncthreads();
        compute_Bnk<36, 36>(As, Vs, acc, wm, wn, g, t);
        __syncthreads();
    }

    #pragma unroll
    for (int mf = 0; mf < 2; mf++) {
        #pragma unroll
        for (int nf = 0; nf < 4; nf++) {
            int d = wn * 32 + nf * 8 + 2 * t;
            #pragma unroll
            for (int h = 0; h < 2; h++) {
                int s = row0 + wm * 32 + mf * 16 + g + h * 8;
                float2* p = (float2*)(g_ao + ((size_t)(b * SS + s)) * (HH * DKV) + hh * 64 + d);
                *p = make_float2(acc[mf][nf][h * 2 + 0], acc[mf][nf][h * 2 + 1]);
            }
        }
    }
}

// ---------------------------------------------------------------------------
extern "C" void kernel_launch(void* const* d_in, const int* in_sizes, int n_in,
                              void* d_out, int out_size)
{
    const float* query = (const float*)d_in[0];
    const float* key   = (const float*)d_in[1];
    const float* value = (const float*)d_in[2];
    const int*   mask  = (const int*)  d_in[3];
    const float* Wq = (const float*)d_in[4];
    const float* bq = (const float*)d_in[5];
    const float* Wk = (const float*)d_in[6];
    const float* bk = (const float*)d_in[7];
    const float* Wv = (const float*)d_in[8];
    const float* bv = (const float*)d_in[9];
    const float* Wo = (const float*)d_in[10];
    const float* bo = (const float*)d_in[11];

    float* out  = (float*)d_out;
    float* attn = out + OUT_OFF;

    dim3 gProj(DD / 64, BB * SS / 128);         // (16, 32)
    gemm_proj<<<gProj, 256>>>(query, Wq, bq, nullptr, 1, 0);
    gemm_proj<<<gProj, 256>>>(key,   Wk, bk, nullptr, 2, 0);
    gemm_proj<<<gProj, 256>>>(value, Wv, bv, nullptr, 3, 0);

    dim3 gScore(SS / 64, SS / 128, BH);         // (32, 16, 32)
    score_kernel<<<gScore, 256>>>(mask, attn);

    softmax_kernel<<<BH * SS, 256>>>(attn);     // 65536 rows

    dim3 gAV(SS / 128, BH);                     // (16, 32)
    gemm_av<<<gAV, 256>>>(attn);

    gemm_proj<<<gProj, 256>>>(nullptr, Wo, bo, out, 0, 1);
}